// round 3
// baseline (speedup 1.0000x reference)
#include <cuda_runtime.h>
#include <cuda_bf16.h>
#include <math.h>

#define DIMX 4096
#define QKVD 6144
#define KVD  1024
#define SEQT 1024
#define NB 2
#define NHEADS 32
#define HD 128

// scratch (allocation-free rule: __device__ globals)
__device__ float g_qkv[(size_t)NB * SEQT * QKVD];   // (2048, 6144)
__device__ float g_att[(size_t)NB * SEQT * DIMX];   // (2048, 4096)

// ---------------------------------------------------------------------------
// SGEMM: C[M,N] = A[M,K] @ W[N,K]^T + bias[N]
// ---------------------------------------------------------------------------
#define BM 128
#define BN 128
#define BKK 16

__global__ __launch_bounds__(256, 2)
void sgemm_nt(const float* __restrict__ A, const float* __restrict__ W,
              const float* __restrict__ bias, float* __restrict__ C,
              int M, int N, int K) {
    __shared__ float As[BKK][BM];
    __shared__ float Bs[BKK][BN];

    const int bx = blockIdx.x;
    const int by = blockIdx.y;
    const int tid = threadIdx.x;
    const int tx = tid % 16;
    const int ty = tid / 16;

    const float* Ab = A + (size_t)(by * BM) * K;
    const float* Wb = W + (size_t)(bx * BN) * K;

    const int lr = tid / 4;
    const int lc = (tid % 4) * 4;

    float acc[8][8];
    #pragma unroll
    for (int i = 0; i < 8; i++)
        #pragma unroll
        for (int j = 0; j < 8; j++) acc[i][j] = 0.0f;

    for (int k0 = 0; k0 < K; k0 += BKK) {
        float4 a0 = *(const float4*)(Ab + (size_t)(lr     ) * K + k0 + lc);
        float4 a1 = *(const float4*)(Ab + (size_t)(lr + 64) * K + k0 + lc);
        float4 w0 = *(const float4*)(Wb + (size_t)(lr     ) * K + k0 + lc);
        float4 w1 = *(const float4*)(Wb + (size_t)(lr + 64) * K + k0 + lc);

        __syncthreads();
        As[lc + 0][lr] = a0.x; As[lc + 1][lr] = a0.y;
        As[lc + 2][lr] = a0.z; As[lc + 3][lr] = a0.w;
        As[lc + 0][lr + 64] = a1.x; As[lc + 1][lr + 64] = a1.y;
        As[lc + 2][lr + 64] = a1.z; As[lc + 3][lr + 64] = a1.w;
        Bs[lc + 0][lr] = w0.x; Bs[lc + 1][lr] = w0.y;
        Bs[lc + 2][lr] = w0.z; Bs[lc + 3][lr] = w0.w;
        Bs[lc + 0][lr + 64] = w1.x; Bs[lc + 1][lr + 64] = w1.y;
        Bs[lc + 2][lr + 64] = w1.z; Bs[lc + 3][lr + 64] = w1.w;
        __syncthreads();

        #pragma unroll
        for (int kk = 0; kk < BKK; kk++) {
            float4 av0 = *(const float4*)(&As[kk][ty * 8]);
            float4 av1 = *(const float4*)(&As[kk][ty * 8 + 4]);
            float4 bv0 = *(const float4*)(&Bs[kk][tx * 8]);
            float4 bv1 = *(const float4*)(&Bs[kk][tx * 8 + 4]);
            float a[8] = {av0.x, av0.y, av0.z, av0.w, av1.x, av1.y, av1.z, av1.w};
            float b[8] = {bv0.x, bv0.y, bv0.z, bv0.w, bv1.x, bv1.y, bv1.z, bv1.w};
            #pragma unroll
            for (int i = 0; i < 8; i++)
                #pragma unroll
                for (int j = 0; j < 8; j++)
                    acc[i][j] = fmaf(a[i], b[j], acc[i][j]);
        }
    }

    const int row0 = by * BM + ty * 8;
    const int col0 = bx * BN + tx * 8;
    float bb[8];
    #pragma unroll
    for (int j = 0; j < 8; j++) bb[j] = bias[col0 + j];

    #pragma unroll
    for (int i = 0; i < 8; i++) {
        float4 r0, r1;
        r0.x = acc[i][0] + bb[0]; r0.y = acc[i][1] + bb[1];
        r0.z = acc[i][2] + bb[2]; r0.w = acc[i][3] + bb[3];
        r1.x = acc[i][4] + bb[4]; r1.y = acc[i][5] + bb[5];
        r1.z = acc[i][6] + bb[6]; r1.w = acc[i][7] + bb[7];
        *(float4*)(C + (size_t)(row0 + i) * N + col0    ) = r0;
        *(float4*)(C + (size_t)(row0 + i) * N + col0 + 4) = r1;
    }
}

// ---------------------------------------------------------------------------
// Flash attention with ELEMENT-WISE repeated K/V (jnp.repeat(..., axis=-1)):
//   head h uses kv slice [h*32, (h+1)*32), each element repeated 4x along d.
//   score(q,k) = sum_j qr[j] * K[k, h*32+j],  qr[j] = scale * sum_{i<4} q[4j+i]
//   out[q, h*128 + 4j + i] = sum_k att[q,k] * V[k, h*32+j]  (same for i=0..3)
// grid (T/8, H, B), 8 warps, one q-row per warp, 32-row K/V tiles.
// ---------------------------------------------------------------------------
#define AT_BK 32

__global__ __launch_bounds__(256, 2)
void attn_kernel(const float* __restrict__ qkv, float* __restrict__ out) {
    __shared__ float Qs[8][32];        // reduced q (32 dims per row)
    __shared__ float Kt[32][33];       // K tile transposed: Kt[j][k], padded
    __shared__ float Vs[AT_BK][32];    // V tile row-major

    const int qt   = blockIdx.x;
    const int h    = blockIdx.y;
    const int b    = blockIdx.z;
    const int tid  = threadIdx.x;
    const int wid  = tid / 32;
    const int lane = tid % 32;

    const int q_row = qt * 8 + wid;
    const float* base = qkv + (size_t)b * SEQT * QKVD;
    const float scale = 0.08838834764831845f;   // 1/sqrt(128)

    // reduced Q: lane j of warp wid computes qr[j] for its q-row
    {
        float4 q4 = *(const float4*)(base + (size_t)q_row * QKVD + h * HD + lane * 4);
        Qs[wid][lane] = (q4.x + q4.y + q4.z + q4.w) * scale;
    }

    float ov = 0.f;                   // output dim j = lane
    float m = -1e30f, l = 0.f;

    const int kmax   = qt * 8 + 7;
    const int ntiles = kmax / AT_BK + 1;

    for (int t = 0; t < ntiles; t++) {
        __syncthreads();
        // K/V tile: 32 rows x 32 floats each (slice h*32 of KVD)
        // each thread: one float4 of K (-> transposed scatter) + one float4 of V
        {
            int r  = tid / 8;             // 0..31
            int d4 = (tid % 8) * 4;       // 0,4,...,28
            const float* rowp = base + (size_t)(t * AT_BK + r) * QKVD + DIMX + h * 32 + d4;
            float4 kk = *(const float4*)(rowp);
            float4 vv = *(const float4*)(rowp + KVD);
            Kt[d4 + 0][r] = kk.x; Kt[d4 + 1][r] = kk.y;
            Kt[d4 + 2][r] = kk.z; Kt[d4 + 3][r] = kk.w;
            *(float4*)(&Vs[r][d4]) = vv;
        }
        __syncthreads();

        // s = dot32(qr, K[:, lane])
        float s = 0.f;
        #pragma unroll
        for (int j = 0; j < 32; j++)
            s = fmaf(Qs[wid][j], Kt[j][lane], s);

        int kg = t * AT_BK + lane;
        if (kg > q_row) s = -1e30f;

        float mt = s;
        #pragma unroll
        for (int off = 16; off > 0; off >>= 1)
            mt = fmaxf(mt, __shfl_xor_sync(0xffffffffu, mt, off));
        float m_new = fmaxf(m, mt);
        float p = __expf(s - m_new);
        float alpha = __expf(m - m_new);
        m = m_new;

        float ps = p;
        #pragma unroll
        for (int off = 16; off > 0; off >>= 1)
            ps += __shfl_xor_sync(0xffffffffu, ps, off);
        l = l * alpha + ps;

        ov *= alpha;
        #pragma unroll
        for (int k = 0; k < AT_BK; k++) {
            float pk = __shfl_sync(0xffffffffu, p, k);
            ov = fmaf(pk, Vs[k][lane], ov);
        }
    }

    float r = ov / l;
    float4 res = make_float4(r, r, r, r);
    *(float4*)(out + (size_t)(b * SEQT + q_row) * DIMX + h * HD + lane * 4) = res;
}

// ---------------------------------------------------------------------------
extern "C" void kernel_launch(void* const* d_in, const int* in_sizes, int n_in,
                              void* d_out, int out_size) {
    const float* x  = (const float*)d_in[0];
    const float* W1 = (const float*)d_in[1];
    const float* b1 = (const float*)d_in[2];
    const float* W2 = (const float*)d_in[3];
    const float* b2 = (const float*)d_in[4];
    float* out = (float*)d_out;

    float* qkv = nullptr;
    float* att = nullptr;
    cudaGetSymbolAddress((void**)&qkv, g_qkv);
    cudaGetSymbolAddress((void**)&att, g_att);

    const int M = NB * SEQT;

    dim3 g1(QKVD / BN, M / BM);
    sgemm_nt<<<g1, 256>>>(x, W1, b1, qkv, M, QKVD, DIMX);

    dim3 g2(SEQT / 8, NHEADS, NB);
    attn_kernel<<<g2, 256>>>(qkv, att);

    dim3 g3(DIMX / BN, M / BM);
    sgemm_nt<<<g3, 256>>>(att, W2, b2, out, M, DIMX, DIMX);
}

// round 5
// speedup vs baseline: 4.3422x; 4.3422x over previous
#include <cuda_runtime.h>
#include <cuda_bf16.h>
#include <cstdint>
#include <math.h>

#define DIMX 4096
#define QKVD 6144
#define KVD  1024
#define SEQT 1024
#define NB 2
#define NHEADS 32
#define HD 128

__device__ float g_qkv[(size_t)NB * SEQT * QKVD];
__device__ float g_att[(size_t)NB * SEQT * DIMX];

// ---------------------------------------------------------------------------
// helpers (baseline PTX only: cp.async + mma.sync tf32, all sm_80+/sm_90 base)
// ---------------------------------------------------------------------------
__device__ __forceinline__ uint32_t smem_u32(const void* p) {
    uint32_t a;
    asm("{ .reg .u64 t; cvta.to.shared.u64 t, %1; cvt.u32.u64 %0, t; }" : "=r"(a) : "l"(p));
    return a;
}
__device__ __forceinline__ uint32_t f2tf32(float f) {
    uint32_t u;
    asm("cvt.rna.tf32.f32 %0, %1;" : "=r"(u) : "f"(f));
    return u;
}
__device__ __forceinline__ void cp16(uint32_t dst, const void* src) {
    asm volatile("cp.async.cg.shared.global [%0], [%1], 16;" :: "r"(dst), "l"(src));
}
#define CP_COMMIT() asm volatile("cp.async.commit_group;" ::: "memory")
#define CP_WAIT(n)  asm volatile("cp.async.wait_group %0;" :: "n"(n) : "memory")

__device__ __forceinline__ void mma_tf32(float* d, const uint32_t* a, const uint32_t* b) {
    asm volatile(
        "mma.sync.aligned.m16n8k8.row.col.f32.tf32.tf32.f32 "
        "{%0,%1,%2,%3}, {%4,%5,%6,%7}, {%8,%9}, {%0,%1,%2,%3};"
        : "+f"(d[0]), "+f"(d[1]), "+f"(d[2]), "+f"(d[3])
        : "r"(a[0]), "r"(a[1]), "r"(a[2]), "r"(a[3]), "r"(b[0]), "r"(b[1]));
}

// ---------------------------------------------------------------------------
// tf32 mma.sync GEMM: C[M,N] = A[M,K] @ W[N,K]^T + bias[N]
// CTA 128x128, BK=32, 8 warps (2M x 4N), warp tile 64x32.
// smem rows padded to 36 floats (stride = 4 mod 32 banks -> conflict-free).
// ---------------------------------------------------------------------------
#define APAD 36
#define TILE_F (128 * APAD)          // floats per (A or B) tile buffer

__global__ __launch_bounds__(256)
void tf32_gemm(const float* __restrict__ A, const float* __restrict__ W,
               const float* __restrict__ bias, float* __restrict__ C,
               int N, int K) {
    extern __shared__ float sm[];

    const int tid  = threadIdx.x;
    const int wid  = tid / 32;
    const int lane = tid % 32;
    const int wm   = wid >> 2;       // 0..1
    const int wn   = wid & 3;        // 0..3
    const int g    = lane >> 2;      // 0..7
    const int t    = lane & 3;       // 0..3
    const int bx   = blockIdx.x;
    const int by   = blockIdx.y;

    const float* Ab = A + (size_t)(by * 128) * K;
    const float* Wb = W + (size_t)(bx * 128) * K;

    float acc[4][4][4];
    #pragma unroll
    for (int i = 0; i < 4; i++)
        #pragma unroll
        for (int j = 0; j < 4; j++)
            #pragma unroll
            for (int c = 0; c < 4; c++) acc[i][j][c] = 0.0f;

    // cp.async staging: 128 rows x 8 chunks(16B) per matrix; 4 chunks/thread each
    const int crow = tid >> 3;           // +0,32,64,96
    const int ckc  = (tid & 7) * 4;      // float offset within row

    const int ntiles = K / 32;

    auto load_tile = [&](int buf, int kt) {
        float* as = sm + buf * 2 * TILE_F;
        float* bs = as + TILE_F;
        uint32_t as_u = smem_u32(as);
        uint32_t bs_u = smem_u32(bs);
        const float* Asrc = Ab + kt * 32;
        const float* Bsrc = Wb + kt * 32;
        #pragma unroll
        for (int i = 0; i < 4; i++) {
            int row = crow + i * 32;
            uint32_t doff = (uint32_t)(row * APAD + ckc) * 4u;
            cp16(as_u + doff, Asrc + (size_t)row * K + ckc);
            cp16(bs_u + doff, Bsrc + (size_t)row * K + ckc);
        }
        CP_COMMIT();
    };

    load_tile(0, 0);

    for (int kt = 0; kt < ntiles; kt++) {
        if (kt + 1 < ntiles) {
            load_tile((kt + 1) & 1, kt + 1);
            CP_WAIT(1);
        } else {
            CP_WAIT(0);
        }
        __syncthreads();

        const float* as = sm + (kt & 1) * 2 * TILE_F + (wm * 64) * APAD;
        const float* bs = sm + (kt & 1) * 2 * TILE_F + TILE_F + (wn * 32) * APAD;

        #pragma unroll
        for (int ks = 0; ks < 4; ks++) {
            const int k0 = ks * 8;
            uint32_t af[4][4], bf[4][2];
            #pragma unroll
            for (int mt = 0; mt < 4; mt++) {
                const float* ap = as + (mt * 16 + g) * APAD + k0 + t;
                af[mt][0] = f2tf32(ap[0]);
                af[mt][1] = f2tf32(ap[8 * APAD]);
                af[mt][2] = f2tf32(ap[4]);
                af[mt][3] = f2tf32(ap[8 * APAD + 4]);
            }
            #pragma unroll
            for (int nt = 0; nt < 4; nt++) {
                const float* bp = bs + (nt * 8 + g) * APAD + k0 + t;
                bf[nt][0] = f2tf32(bp[0]);
                bf[nt][1] = f2tf32(bp[4]);
            }
            #pragma unroll
            for (int mt = 0; mt < 4; mt++)
                #pragma unroll
                for (int nt = 0; nt < 4; nt++)
                    mma_tf32(acc[mt][nt], af[mt], bf[nt]);
        }
        __syncthreads();
    }

    // epilogue: float2 stores, bias added
    #pragma unroll
    for (int nt = 0; nt < 4; nt++) {
        const int col = bx * 128 + wn * 32 + nt * 8 + 2 * t;
        float2 bv = *(const float2*)(bias + col);
        #pragma unroll
        for (int mt = 0; mt < 4; mt++) {
            const int row = by * 128 + wm * 64 + mt * 16 + g;
            float2 r0, r1;
            r0.x = acc[mt][nt][0] + bv.x;
            r0.y = acc[mt][nt][1] + bv.y;
            r1.x = acc[mt][nt][2] + bv.x;
            r1.y = acc[mt][nt][3] + bv.y;
            *(float2*)(C + (size_t)row * N + col)       = r0;
            *(float2*)(C + (size_t)(row + 8) * N + col) = r1;
        }
    }
}

#define GEMM_SMEM (4 * TILE_F * 4)   // 73728 bytes

// ---------------------------------------------------------------------------
// Flash attention with element-wise repeated K/V (unchanged, correct)
// ---------------------------------------------------------------------------
#define AT_BK 32

__global__ __launch_bounds__(256, 2)
void attn_kernel(const float* __restrict__ qkv, float* __restrict__ out) {
    __shared__ float Qs[8][32];
    __shared__ float Kt[32][33];
    __shared__ float Vs[AT_BK][32];

    const int qt   = blockIdx.x;
    const int h    = blockIdx.y;
    const int b    = blockIdx.z;
    const int tid  = threadIdx.x;
    const int wid  = tid / 32;
    const int lane = tid % 32;

    const int q_row = qt * 8 + wid;
    const float* base = qkv + (size_t)b * SEQT * QKVD;
    const float scale = 0.08838834764831845f;

    {
        float4 q4 = *(const float4*)(base + (size_t)q_row * QKVD + h * HD + lane * 4);
        Qs[wid][lane] = (q4.x + q4.y + q4.z + q4.w) * scale;
    }

    float ov = 0.f;
    float m = -1e30f, l = 0.f;

    const int kmax   = qt * 8 + 7;
    const int ntiles = kmax / AT_BK + 1;

    for (int tt = 0; tt < ntiles; tt++) {
        __syncthreads();
        {
            int r  = tid / 8;
            int d4 = (tid % 8) * 4;
            const float* rowp = base + (size_t)(tt * AT_BK + r) * QKVD + DIMX + h * 32 + d4;
            float4 kk = *(const float4*)(rowp);
            float4 vv = *(const float4*)(rowp + KVD);
            Kt[d4 + 0][r] = kk.x; Kt[d4 + 1][r] = kk.y;
            Kt[d4 + 2][r] = kk.z; Kt[d4 + 3][r] = kk.w;
            *(float4*)(&Vs[r][d4]) = vv;
        }
        __syncthreads();

        float s = 0.f;
        #pragma unroll
        for (int j = 0; j < 32; j++)
            s = fmaf(Qs[wid][j], Kt[j][lane], s);

        int kg = tt * AT_BK + lane;
        if (kg > q_row) s = -1e30f;

        float mt = s;
        #pragma unroll
        for (int off = 16; off > 0; off >>= 1)
            mt = fmaxf(mt, __shfl_xor_sync(0xffffffffu, mt, off));
        float m_new = fmaxf(m, mt);
        float p = __expf(s - m_new);
        float alpha = __expf(m - m_new);
        m = m_new;

        float ps = p;
        #pragma unroll
        for (int off = 16; off > 0; off >>= 1)
            ps += __shfl_xor_sync(0xffffffffu, ps, off);
        l = l * alpha + ps;

        ov *= alpha;
        #pragma unroll
        for (int k = 0; k < AT_BK; k++) {
            float pk = __shfl_sync(0xffffffffu, p, k);
            ov = fmaf(pk, Vs[k][lane], ov);
        }
    }

    float r = ov / l;
    float4 res = make_float4(r, r, r, r);
    *(float4*)(out + (size_t)(b * SEQT + q_row) * DIMX + h * HD + lane * 4) = res;
}

// ---------------------------------------------------------------------------
extern "C" void kernel_launch(void* const* d_in, const int* in_sizes, int n_in,
                              void* d_out, int out_size) {
    const float* x  = (const float*)d_in[0];
    const float* W1 = (const float*)d_in[1];
    const float* b1 = (const float*)d_in[2];
    const float* W2 = (const float*)d_in[3];
    const float* b2 = (const float*)d_in[4];
    float* out = (float*)d_out;

    float* qkv = nullptr;
    float* att = nullptr;
    cudaGetSymbolAddress((void**)&qkv, g_qkv);
    cudaGetSymbolAddress((void**)&att, g_att);

    cudaFuncSetAttribute(tf32_gemm, cudaFuncAttributeMaxDynamicSharedMemorySize, GEMM_SMEM);

    const int M = NB * SEQT;   // 2048

    dim3 g1(QKVD / 128, M / 128);
    tf32_gemm<<<g1, 256, GEMM_SMEM>>>(x, W1, b1, qkv, QKVD, DIMX);

    dim3 g2(SEQT / 8, NHEADS, NB);
    attn_kernel<<<g2, 256>>>(qkv, att);

    dim3 g3(DIMX / 128, M / 128);
    tf32_gemm<<<g3, 256, GEMM_SMEM>>>(att, W2, b2, out, DIMX, DIMX);
}

// round 6
// speedup vs baseline: 5.1270x; 1.1808x over previous
#include <cuda_runtime.h>
#include <cuda_bf16.h>
#include <cstdint>
#include <math.h>

#define DIMX 4096
#define QKVD 6144
#define KVD  1024
#define SEQT 1024
#define NB 2
#define NHEADS 32
#define HD 128

__device__ float g_qkv[(size_t)NB * SEQT * QKVD];
__device__ float g_att[(size_t)NB * SEQT * DIMX];
// tf32-pre-rounded copies of GEMM inputs
__device__ float g_xr[(size_t)NB * SEQT * DIMX];
__device__ float g_w1r[(size_t)QKVD * DIMX];
__device__ float g_w2r[(size_t)DIMX * DIMX];

// ---------------------------------------------------------------------------
__device__ __forceinline__ uint32_t smem_u32(const void* p) {
    uint32_t a;
    asm("{ .reg .u64 t; cvta.to.shared.u64 t, %1; cvt.u32.u64 %0, t; }" : "=r"(a) : "l"(p));
    return a;
}
__device__ __forceinline__ float f2tf32f(float f) {
    uint32_t u;
    asm("cvt.rna.tf32.f32 %0, %1;" : "=r"(u) : "f"(f));
    return __uint_as_float(u);
}
__device__ __forceinline__ void cp16(uint32_t dst, const void* src) {
    asm volatile("cp.async.cg.shared.global [%0], [%1], 16;" :: "r"(dst), "l"(src));
}
#define CP_COMMIT() asm volatile("cp.async.commit_group;" ::: "memory")
#define CP_WAIT(n)  asm volatile("cp.async.wait_group %0;" :: "n"(n) : "memory")

__device__ __forceinline__ void mma_tf32(float* d, const uint32_t* a, const uint32_t* b) {
    asm volatile(
        "mma.sync.aligned.m16n8k8.row.col.f32.tf32.tf32.f32 "
        "{%0,%1,%2,%3}, {%4,%5,%6,%7}, {%8,%9}, {%0,%1,%2,%3};"
        : "+f"(d[0]), "+f"(d[1]), "+f"(d[2]), "+f"(d[3])
        : "r"(a[0]), "r"(a[1]), "r"(a[2]), "r"(a[3]), "r"(b[0]), "r"(b[1]));
}

// ---------------------------------------------------------------------------
// elementwise tf32 pre-round (float4 grid-stride)
// ---------------------------------------------------------------------------
__global__ void round_tf32(const float* __restrict__ in, float* __restrict__ out, int n4) {
    int i = blockIdx.x * blockDim.x + threadIdx.x;
    if (i < n4) {
        float4 v = ((const float4*)in)[i];
        v.x = f2tf32f(v.x); v.y = f2tf32f(v.y);
        v.z = f2tf32f(v.z); v.w = f2tf32f(v.w);
        ((float4*)out)[i] = v;
    }
}

// ---------------------------------------------------------------------------
// tf32 mma.sync GEMM: C[M,N] = A[M,K] @ W[N,K]^T + bias[N]
// CTA tile 128(M) x 256(N), BK=32, 8 warps (2M x 4N), warp tile 64x64.
// Inputs MUST already be tf32-rounded (mma truncation then lossless).
// smem rows padded to 36 floats (stride 4 mod 32 banks -> conflict-free).
// ---------------------------------------------------------------------------
#define APAD 36
#define ATILE_F (128 * APAD)
#define BTILE_F (256 * APAD)
#define STAGE_F (ATILE_F + BTILE_F)
#define GEMM_SMEM (2 * STAGE_F * 4)   // 110592 B

__global__ __launch_bounds__(256, 1)
void tf32_gemm(const float* __restrict__ A, const float* __restrict__ W,
               const float* __restrict__ bias, float* __restrict__ C,
               int N, int K) {
    extern __shared__ float sm[];

    const int tid  = threadIdx.x;
    const int wid  = tid / 32;
    const int lane = tid % 32;
    const int wm   = wid >> 2;       // 0..1
    const int wn   = wid & 3;        // 0..3
    const int g    = lane >> 2;      // 0..7
    const int t    = lane & 3;       // 0..3
    const int bx   = blockIdx.x;     // N tile (256)
    const int by   = blockIdx.y;     // M tile (128)

    const float* Ab = A + (size_t)(by * 128) * K;
    const float* Wb = W + (size_t)(bx * 256) * K;

    float acc[4][8][4];
    #pragma unroll
    for (int i = 0; i < 4; i++)
        #pragma unroll
        for (int j = 0; j < 8; j++)
            #pragma unroll
            for (int c = 0; c < 4; c++) acc[i][j][c] = 0.0f;

    const int crow = tid >> 3;          // 0..31
    const int ckc  = (tid & 7) * 4;     // float col within 32

    const int ntiles = K / 32;

    auto load_tile = [&](int buf, int kt) {
        float* as = sm + buf * STAGE_F;
        float* bs = as + ATILE_F;
        uint32_t as_u = smem_u32(as);
        uint32_t bs_u = smem_u32(bs);
        const float* Asrc = Ab + kt * 32;
        const float* Bsrc = Wb + kt * 32;
        #pragma unroll
        for (int i = 0; i < 4; i++) {
            int row = crow + i * 32;
            cp16(as_u + (uint32_t)(row * APAD + ckc) * 4u, Asrc + (size_t)row * K + ckc);
        }
        #pragma unroll
        for (int i = 0; i < 8; i++) {
            int row = crow + i * 32;
            cp16(bs_u + (uint32_t)(row * APAD + ckc) * 4u, Bsrc + (size_t)row * K + ckc);
        }
        CP_COMMIT();
    };

    load_tile(0, 0);

    for (int kt = 0; kt < ntiles; kt++) {
        if (kt + 1 < ntiles) {
            load_tile((kt + 1) & 1, kt + 1);
            CP_WAIT(1);
        } else {
            CP_WAIT(0);
        }
        __syncthreads();

        const float* as = sm + (kt & 1) * STAGE_F + (wm * 64) * APAD;
        const float* bs = sm + (kt & 1) * STAGE_F + ATILE_F + (wn * 64) * APAD;

        #pragma unroll
        for (int ks = 0; ks < 4; ks++) {
            const int k0 = ks * 8;
            uint32_t af[4][4], bf[8][2];
            #pragma unroll
            for (int mt = 0; mt < 4; mt++) {
                const uint32_t* ap = (const uint32_t*)(as + (mt * 16 + g) * APAD + k0 + t);
                af[mt][0] = ap[0];
                af[mt][1] = ap[8 * APAD];
                af[mt][2] = ap[4];
                af[mt][3] = ap[8 * APAD + 4];
            }
            #pragma unroll
            for (int nt = 0; nt < 8; nt++) {
                const uint32_t* bp = (const uint32_t*)(bs + (nt * 8 + g) * APAD + k0 + t);
                bf[nt][0] = bp[0];
                bf[nt][1] = bp[4];
            }
            #pragma unroll
            for (int mt = 0; mt < 4; mt++)
                #pragma unroll
                for (int nt = 0; nt < 8; nt++)
                    mma_tf32(acc[mt][nt], af[mt], bf[nt]);
        }
        __syncthreads();
    }

    #pragma unroll
    for (int nt = 0; nt < 8; nt++) {
        const int col = bx * 256 + wn * 64 + nt * 8 + 2 * t;
        float2 bv = *(const float2*)(bias + col);
        #pragma unroll
        for (int mt = 0; mt < 4; mt++) {
            const int row = by * 128 + wm * 64 + mt * 16 + g;
            float2 r0, r1;
            r0.x = acc[mt][nt][0] + bv.x;
            r0.y = acc[mt][nt][1] + bv.y;
            r1.x = acc[mt][nt][2] + bv.x;
            r1.y = acc[mt][nt][3] + bv.y;
            *(float2*)(C + (size_t)row * N + col)       = r0;
            *(float2*)(C + (size_t)(row + 8) * N + col) = r1;
        }
    }
}

// ---------------------------------------------------------------------------
// Flash attention, element-wise repeated K/V. 32 q-rows per block,
// 8 warps x 4 q-rows; K/V tile loaded once per block (4x reuse vs R5).
// Epilogue rounds output to tf32 (it feeds the tf32 GEMM2).
// ---------------------------------------------------------------------------
#define AT_BK 32

__global__ __launch_bounds__(256, 2)
void attn_kernel(const float* __restrict__ qkv, float* __restrict__ out) {
    __shared__ float Qs[32][32];
    __shared__ float Kt[32][33];
    __shared__ float Vs[AT_BK][32];

    const int qt   = blockIdx.x;       // 32-row q tile
    const int h    = blockIdx.y;
    const int b    = blockIdx.z;
    const int tid  = threadIdx.x;
    const int wid  = tid / 32;
    const int lane = tid % 32;

    const float* base = qkv + (size_t)b * SEQT * QKVD;
    const float scale = 0.08838834764831845f;

    // reduced Q for 32 rows: warp w handles row (w + 8*it), lane = entry
    #pragma unroll
    for (int it = 0; it < 4; it++) {
        int r = it * 8 + wid;
        float4 q4 = *(const float4*)(base + (size_t)(qt * 32 + r) * QKVD + h * HD + lane * 4);
        Qs[r][lane] = (q4.x + q4.y + q4.z + q4.w) * scale;
    }

    float ov[4] = {0.f, 0.f, 0.f, 0.f};
    float m[4] = {-1e30f, -1e30f, -1e30f, -1e30f};
    float l[4] = {0.f, 0.f, 0.f, 0.f};
    const int qr0 = qt * 32 + wid * 4;      // first q row of this warp

    const int ntiles = qt + 1;

    for (int tt = 0; tt < ntiles; tt++) {
        __syncthreads();
        {
            int r  = tid / 8;
            int d4 = (tid % 8) * 4;
            const float* rowp = base + (size_t)(tt * AT_BK + r) * QKVD + DIMX + h * 32 + d4;
            float4 kk = *(const float4*)(rowp);
            float4 vv = *(const float4*)(rowp + KVD);
            Kt[d4 + 0][r] = kk.x; Kt[d4 + 1][r] = kk.y;
            Kt[d4 + 2][r] = kk.z; Kt[d4 + 3][r] = kk.w;
            *(float4*)(&Vs[r][d4]) = vv;
        }
        __syncthreads();

        const int kg = tt * AT_BK + lane;

        #pragma unroll
        for (int i = 0; i < 4; i++) {
            const int q_row = qr0 + i;
            float s = 0.f;
            const float* qrow = Qs[wid * 4 + i];
            #pragma unroll
            for (int j = 0; j < 32; j++)
                s = fmaf(qrow[j], Kt[j][lane], s);
            if (kg > q_row) s = -1e30f;

            float mt = s;
            #pragma unroll
            for (int off = 16; off > 0; off >>= 1)
                mt = fmaxf(mt, __shfl_xor_sync(0xffffffffu, mt, off));
            float m_new = fmaxf(m[i], mt);
            float p = __expf(s - m_new);
            float alpha = __expf(m[i] - m_new);
            m[i] = m_new;

            float ps = p;
            #pragma unroll
            for (int off = 16; off > 0; off >>= 1)
                ps += __shfl_xor_sync(0xffffffffu, ps, off);
            l[i] = l[i] * alpha + ps;

            ov[i] *= alpha;
            #pragma unroll
            for (int k = 0; k < AT_BK; k++) {
                float pk = __shfl_sync(0xffffffffu, p, k);
                ov[i] = fmaf(pk, Vs[k][lane], ov[i]);
            }
        }
    }

    #pragma unroll
    for (int i = 0; i < 4; i++) {
        float r = f2tf32f(ov[i] / l[i]);   // pre-round for tf32 GEMM2
        float4 res = make_float4(r, r, r, r);
        *(float4*)(out + (size_t)(b * SEQT + qr0 + i) * DIMX + h * HD + lane * 4) = res;
    }
}

// ---------------------------------------------------------------------------
extern "C" void kernel_launch(void* const* d_in, const int* in_sizes, int n_in,
                              void* d_out, int out_size) {
    const float* x  = (const float*)d_in[0];
    const float* W1 = (const float*)d_in[1];
    const float* b1 = (const float*)d_in[2];
    const float* W2 = (const float*)d_in[3];
    const float* b2 = (const float*)d_in[4];
    float* out = (float*)d_out;

    float *qkv, *att, *xr, *w1r, *w2r;
    cudaGetSymbolAddress((void**)&qkv, g_qkv);
    cudaGetSymbolAddress((void**)&att, g_att);
    cudaGetSymbolAddress((void**)&xr,  g_xr);
    cudaGetSymbolAddress((void**)&w1r, g_w1r);
    cudaGetSymbolAddress((void**)&w2r, g_w2r);

    cudaFuncSetAttribute(tf32_gemm, cudaFuncAttributeMaxDynamicSharedMemorySize, GEMM_SMEM);

    const int M = NB * SEQT;   // 2048

    // pre-round GEMM inputs to tf32
    {
        int n4 = (M * DIMX) / 4;
        round_tf32<<<(n4 + 255) / 256, 256>>>(x, xr, n4);
        n4 = (QKVD * DIMX) / 4;
        round_tf32<<<(n4 + 255) / 256, 256>>>(W1, w1r, n4);
        n4 = (DIMX * DIMX) / 4;
        round_tf32<<<(n4 + 255) / 256, 256>>>(W2, w2r, n4);
    }

    dim3 g1(QKVD / 256, M / 128);
    tf32_gemm<<<g1, 256, GEMM_SMEM>>>(xr, w1r, b1, qkv, QKVD, DIMX);

    dim3 g2(SEQT / 32, NHEADS, NB);
    attn_kernel<<<g2, 256>>>(qkv, att);

    dim3 g3(DIMX / 256, M / 128);
    tf32_gemm<<<g3, 256, GEMM_SMEM>>>(att, w2r, b2, out, DIMX, DIMX);
}

// round 9
// speedup vs baseline: 5.1344x; 1.0014x over previous
#include <cuda_runtime.h>
#include <cuda_bf16.h>
#include <cstdint>
#include <math.h>

#define DIMX 4096
#define QKVD 6144
#define KVD  1024
#define SEQT 1024
#define NB 2
#define NHEADS 32
#define HD 128

__device__ float g_qkv[(size_t)NB * SEQT * QKVD];
__device__ float g_att[(size_t)NB * SEQT * DIMX];
__device__ float g_xr[(size_t)NB * SEQT * DIMX];
__device__ float g_w1r[(size_t)QKVD * DIMX];
__device__ float g_w2r[(size_t)DIMX * DIMX];

// ---------------------------------------------------------------------------
__device__ __forceinline__ uint32_t smem_u32(const void* p) {
    uint32_t a;
    asm("{ .reg .u64 t; cvta.to.shared.u64 t, %1; cvt.u32.u64 %0, t; }" : "=r"(a) : "l"(p));
    return a;
}
__device__ __forceinline__ float f2tf32f(float f) {
    uint32_t u;
    asm("cvt.rna.tf32.f32 %0, %1;" : "=r"(u) : "f"(f));
    return __uint_as_float(u);
}
__device__ __forceinline__ void cp16(uint32_t dst, const void* src) {
    asm volatile("cp.async.cg.shared.global [%0], [%1], 16;" :: "r"(dst), "l"(src));
}
#define CP_COMMIT() asm volatile("cp.async.commit_group;" ::: "memory")
#define CP_WAIT(n)  asm volatile("cp.async.wait_group %0;" :: "n"(n) : "memory")

__device__ __forceinline__ void mma_tf32(float* d, const uint32_t* a, const uint32_t* b) {
    asm volatile(
        "mma.sync.aligned.m16n8k8.row.col.f32.tf32.tf32.f32 "
        "{%0,%1,%2,%3}, {%4,%5,%6,%7}, {%8,%9}, {%0,%1,%2,%3};"
        : "+f"(d[0]), "+f"(d[1]), "+f"(d[2]), "+f"(d[3])
        : "r"(a[0]), "r"(a[1]), "r"(a[2]), "r"(a[3]), "r"(b[0]), "r"(b[1]));
}

// ---------------------------------------------------------------------------
__global__ void round_tf32(const float* __restrict__ in, float* __restrict__ out, int n4) {
    int i = blockIdx.x * blockDim.x + threadIdx.x;
    if (i < n4) {
        float4 v = ((const float4*)in)[i];
        v.x = f2tf32f(v.x); v.y = f2tf32f(v.y);
        v.z = f2tf32f(v.z); v.w = f2tf32f(v.w);
        ((float4*)out)[i] = v;
    }
}

// ---------------------------------------------------------------------------
// tf32 mma.sync GEMM: C[M,N] = A[M,K] @ W[N,K]^T + bias[N]
// CTA 128(M) x 256(N), BK=32, 8 warps (2M x 4N), warp tile 64x64.
// 3-stage cp.async pipeline, ONE __syncthreads per k-tile.
// Inputs must be tf32-pre-rounded. smem rows padded to 36 floats.
// ---------------------------------------------------------------------------
#define APAD 36
#define ATILE_F (128 * APAD)
#define BTILE_F (256 * APAD)
#define STAGE_F (ATILE_F + BTILE_F)
#define STAGES 3
#define GEMM_SMEM (STAGES * STAGE_F * 4)   // 165888 B

__global__ __launch_bounds__(256, 1)
void tf32_gemm(const float* __restrict__ A, const float* __restrict__ W,
               const float* __restrict__ bias, float* __restrict__ C,
               int N, int K) {
    extern __shared__ float sm[];

    const int tid  = threadIdx.x;
    const int wid  = tid / 32;
    const int lane = tid % 32;
    const int wm   = wid >> 2;
    const int wn   = wid & 3;
    const int g    = lane >> 2;
    const int t    = lane & 3;
    const int bx   = blockIdx.x;
    const int by   = blockIdx.y;

    const float* Ab = A + (size_t)(by * 128) * K;
    const float* Wb = W + (size_t)(bx * 256) * K;

    float acc[4][8][4];
    #pragma unroll
    for (int i = 0; i < 4; i++)
        #pragma unroll
        for (int j = 0; j < 8; j++)
            #pragma unroll
            for (int c = 0; c < 4; c++) acc[i][j][c] = 0.0f;

    const int crow = tid >> 3;
    const int ckc  = (tid & 7) * 4;

    const int ntiles = K / 32;

    auto load_tile = [&](int buf, int kt) {
        float* as = sm + buf * STAGE_F;
        float* bs = as + ATILE_F;
        uint32_t as_u = smem_u32(as);
        uint32_t bs_u = smem_u32(bs);
        const float* Asrc = Ab + kt * 32;
        const float* Bsrc = Wb + kt * 32;
        #pragma unroll
        for (int i = 0; i < 4; i++) {
            int row = crow + i * 32;
            cp16(as_u + (uint32_t)(row * APAD + ckc) * 4u, Asrc + (size_t)row * K + ckc);
        }
        #pragma unroll
        for (int i = 0; i < 8; i++) {
            int row = crow + i * 32;
            cp16(bs_u + (uint32_t)(row * APAD + ckc) * 4u, Bsrc + (size_t)row * K + ckc);
        }
        CP_COMMIT();
    };

    load_tile(0, 0);
    load_tile(1, 1);

    for (int kt = 0; kt < ntiles; kt++) {
        CP_WAIT(1);          // tile kt resident (only kt+1 may remain in flight)
        __syncthreads();     // tile kt visible to all; all warps done with tile kt-1

        if (kt + 2 < ntiles)
            load_tile((kt + 2) % STAGES, kt + 2);   // overlaps compute of kt

        const int buf = kt % STAGES;
        const float* as = sm + buf * STAGE_F + (wm * 64) * APAD;
        const float* bs = sm + buf * STAGE_F + ATILE_F + (wn * 64) * APAD;

        #pragma unroll
        for (int ks = 0; ks < 4; ks++) {
            const int k0 = ks * 8;
            uint32_t af[4][4], bf[8][2];
            #pragma unroll
            for (int mt = 0; mt < 4; mt++) {
                const uint32_t* ap = (const uint32_t*)(as + (mt * 16 + g) * APAD + k0 + t);
                af[mt][0] = ap[0];
                af[mt][1] = ap[8 * APAD];
                af[mt][2] = ap[4];
                af[mt][3] = ap[8 * APAD + 4];
            }
            #pragma unroll
            for (int nt = 0; nt < 8; nt++) {
                const uint32_t* bp = (const uint32_t*)(bs + (nt * 8 + g) * APAD + k0 + t);
                bf[nt][0] = bp[0];
                bf[nt][1] = bp[4];
            }
            #pragma unroll
            for (int mt = 0; mt < 4; mt++)
                #pragma unroll
                for (int nt = 0; nt < 8; nt++)
                    mma_tf32(acc[mt][nt], af[mt], bf[nt]);
        }
    }

    #pragma unroll
    for (int nt = 0; nt < 8; nt++) {
        const int col = bx * 256 + wn * 64 + nt * 8 + 2 * t;
        float2 bv = *(const float2*)(bias + col);
        #pragma unroll
        for (int mt = 0; mt < 4; mt++) {
            const int row = by * 128 + wm * 64 + mt * 16 + g;
            float2 r0, r1;
            r0.x = acc[mt][nt][0] + bv.x;
            r0.y = acc[mt][nt][1] + bv.y;
            r1.x = acc[mt][nt][2] + bv.x;
            r1.y = acc[mt][nt][3] + bv.y;
            *(float2*)(C + (size_t)row * N + col)       = r0;
            *(float2*)(C + (size_t)(row + 8) * N + col) = r1;
        }
    }
}

// ---------------------------------------------------------------------------
// Flash attention, element-wise repeated K/V (unchanged from R6)
// ---------------------------------------------------------------------------
#define AT_BK 32

__global__ __launch_bounds__(256, 2)
void attn_kernel(const float* __restrict__ qkv, float* __restrict__ out) {
    __shared__ float Qs[32][32];
    __shared__ float Kt[32][33];
    __shared__ float Vs[AT_BK][32];

    const int qt   = blockIdx.x;
    const int h    = blockIdx.y;
    const int b    = blockIdx.z;
    const int tid  = threadIdx.x;
    const int wid  = tid / 32;
    const int lane = tid % 32;

    const float* base = qkv + (size_t)b * SEQT * QKVD;
    const float scale = 0.08838834764831845f;

    #pragma unroll
    for (int it = 0; it < 4; it++) {
        int r = it * 8 + wid;
        float4 q4 = *(const float4*)(base + (size_t)(qt * 32 + r) * QKVD + h * HD + lane * 4);
        Qs[r][lane] = (q4.x + q4.y + q4.z + q4.w) * scale;
    }

    float ov[4] = {0.f, 0.f, 0.f, 0.f};
    float m[4] = {-1e30f, -1e30f, -1e30f, -1e30f};
    float l[4] = {0.f, 0.f, 0.f, 0.f};
    const int qr0 = qt * 32 + wid * 4;

    const int ntiles = qt + 1;

    for (int tt = 0; tt < ntiles; tt++) {
        __syncthreads();
        {
            int r  = tid / 8;
            int d4 = (tid % 8) * 4;
            const float* rowp = base + (size_t)(tt * AT_BK + r) * QKVD + DIMX + h * 32 + d4;
            float4 kk = *(const float4*)(rowp);
            float4 vv = *(const float4*)(rowp + KVD);
            Kt[d4 + 0][r] = kk.x; Kt[d4 + 1][r] = kk.y;
            Kt[d4 + 2][r] = kk.z; Kt[d4 + 3][r] = kk.w;
            *(float4*)(&Vs[r][d4]) = vv;
        }
        __syncthreads();

        const int kg = tt * AT_BK + lane;

        #pragma unroll
        for (int i = 0; i < 4; i++) {
            const int q_row = qr0 + i;
            float s = 0.f;
            const float* qrow = Qs[wid * 4 + i];
            #pragma unroll
            for (int j = 0; j < 32; j++)
                s = fmaf(qrow[j], Kt[j][lane], s);
            if (kg > q_row) s = -1e30f;

            float mt = s;
            #pragma unroll
            for (int off = 16; off > 0; off >>= 1)
                mt = fmaxf(mt, __shfl_xor_sync(0xffffffffu, mt, off));
            float m_new = fmaxf(m[i], mt);
            float p = __expf(s - m_new);
            float alpha = __expf(m[i] - m_new);
            m[i] = m_new;

            float ps = p;
            #pragma unroll
            for (int off = 16; off > 0; off >>= 1)
                ps += __shfl_xor_sync(0xffffffffu, ps, off);
            l[i] = l[i] * alpha + ps;

            ov[i] *= alpha;
            #pragma unroll
            for (int k = 0; k < AT_BK; k++) {
                float pk = __shfl_sync(0xffffffffu, p, k);
                ov[i] = fmaf(pk, Vs[k][lane], ov[i]);
            }
        }
    }

    #pragma unroll
    for (int i = 0; i < 4; i++) {
        float r = f2tf32f(ov[i] / l[i]);
        float4 res = make_float4(r, r, r, r);
        *(float4*)(out + (size_t)(b * SEQT + qr0 + i) * DIMX + h * HD + lane * 4) = res;
    }
}

// ---------------------------------------------------------------------------
extern "C" void kernel_launch(void* const* d_in, const int* in_sizes, int n_in,
                              void* d_out, int out_size) {
    const float* x  = (const float*)d_in[0];
    const float* W1 = (const float*)d_in[1];
    const float* b1 = (const float*)d_in[2];
    const float* W2 = (const float*)d_in[3];
    const float* b2 = (const float*)d_in[4];
    float* out = (float*)d_out;

    float *qkv, *att, *xr, *w1r, *w2r;
    cudaGetSymbolAddress((void**)&qkv, g_qkv);
    cudaGetSymbolAddress((void**)&att, g_att);
    cudaGetSymbolAddress((void**)&xr,  g_xr);
    cudaGetSymbolAddress((void**)&w1r, g_w1r);
    cudaGetSymbolAddress((void**)&w2r, g_w2r);

    cudaFuncSetAttribute(tf32_gemm, cudaFuncAttributeMaxDynamicSharedMemorySize, GEMM_SMEM);

    const int M = NB * SEQT;

    {
        int n4 = (M * DIMX) / 4;
        round_tf32<<<(n4 + 255) / 256, 256>>>(x, xr, n4);
        n4 = (QKVD * DIMX) / 4;
        round_tf32<<<(n4 + 255) / 256, 256>>>(W1, w1r, n4);
        n4 = (DIMX * DIMX) / 4;
        round_tf32<<<(n4 + 255) / 256, 256>>>(W2, w2r, n4);
    }

    dim3 g1(QKVD / 256, M / 128);
    tf32_gemm<<<g1, 256, GEMM_SMEM>>>(xr, w1r, b1, qkv, QKVD, DIMX);

    dim3 g2(SEQT / 32, NHEADS, NB);
    attn_kernel<<<g2, 256>>>(qkv, att);

    dim3 g3(DIMX / 256, M / 128);
    tf32_gemm<<<g3, 256, GEMM_SMEM>>>(att, w2r, b2, out, DIMX, DIMX);
}

// round 10
// speedup vs baseline: 5.9126x; 1.1516x over previous
#include <cuda_runtime.h>
#include <cuda_bf16.h>
#include <cstdint>
#include <math.h>

#define DIMX 4096
#define QKVD 6144
#define KVD  1024
#define SEQT 1024
#define NB 2
#define NHEADS 32
#define HD 128

__device__ float g_qkv[(size_t)NB * SEQT * QKVD];
__device__ float g_att[(size_t)NB * SEQT * DIMX];   // K-permuted layout
__device__ float g_xr[(size_t)NB * SEQT * DIMX];    // tf32-rounded + K-permuted
__device__ float g_w1r[(size_t)QKVD * DIMX];        // tf32-rounded + K-permuted
__device__ float g_w2r[(size_t)DIMX * DIMX];        // tf32-rounded + K-permuted

// ---------------------------------------------------------------------------
__device__ __forceinline__ uint32_t smem_u32(const void* p) {
    uint32_t a;
    asm("{ .reg .u64 t; cvta.to.shared.u64 t, %1; cvt.u32.u64 %0, t; }" : "=r"(a) : "l"(p));
    return a;
}
__device__ __forceinline__ float f2tf32f(float f) {
    uint32_t u;
    asm("cvt.rna.tf32.f32 %0, %1;" : "=r"(u) : "f"(f));
    return __uint_as_float(u);
}
__device__ __forceinline__ void cp16(uint32_t dst, const void* src) {
    asm volatile("cp.async.cg.shared.global [%0], [%1], 16;" :: "r"(dst), "l"(src));
}
#define CP_COMMIT() asm volatile("cp.async.commit_group;" ::: "memory")
#define CP_WAIT(n)  asm volatile("cp.async.wait_group %0;" :: "n"(n) : "memory")

__device__ __forceinline__ void mma_tf32(float* d, const uint32_t* a, const uint32_t* b) {
    asm volatile(
        "mma.sync.aligned.m16n8k8.row.col.f32.tf32.tf32.f32 "
        "{%0,%1,%2,%3}, {%4,%5,%6,%7}, {%8,%9}, {%0,%1,%2,%3};"
        : "+f"(d[0]), "+f"(d[1]), "+f"(d[2]), "+f"(d[3])
        : "r"(a[0]), "r"(a[1]), "r"(a[2]), "r"(a[3]), "r"(b[0]), "r"(b[1]));
}

// ---------------------------------------------------------------------------
// pre-round to tf32 AND interleave each k8 group: mem = [c0,c4,c1,c5,c2,c6,c3,c7]
// -> fragment pair (k=t, k=t+4) is contiguous in memory (enables LDS.64).
// ---------------------------------------------------------------------------
__global__ void round_perm(const float* __restrict__ in, float* __restrict__ out, int n8) {
    int i = blockIdx.x * blockDim.x + threadIdx.x;
    if (i < n8) {
        float4 a = ((const float4*)in)[2 * i];
        float4 b = ((const float4*)in)[2 * i + 1];
        float4 o0, o1;
        o0.x = f2tf32f(a.x); o0.y = f2tf32f(b.x);   // c0, c4
        o0.z = f2tf32f(a.y); o0.w = f2tf32f(b.y);   // c1, c5
        o1.x = f2tf32f(a.z); o1.y = f2tf32f(b.z);   // c2, c6
        o1.z = f2tf32f(a.w); o1.w = f2tf32f(b.w);   // c3, c7
        ((float4*)out)[2 * i]     = o0;
        ((float4*)out)[2 * i + 1] = o1;
    }
}

// ---------------------------------------------------------------------------
// tf32 mma.sync GEMM: C[M,N] = A[M,K] @ W[N,K]^T + bias[N]
// CTA 128x128, 128 threads (4 warps, 2x2 of 64x64 warp tiles), BK=32,
// 2-stage cp.async, 2 CTAs/SM. Inputs tf32-rounded + k8-interleaved.
// smem rows padded to 40 floats -> conflict-free LDS.64 fragments.
// ---------------------------------------------------------------------------
#define APAD 40
#define TILE_F (128 * APAD)                // floats per A (or B) tile
#define STAGE_F (2 * TILE_F)
#define GEMM_SMEM (2 * STAGE_F * 4)        // 81920 B

__global__ __launch_bounds__(128, 2)
void tf32_gemm(const float* __restrict__ A, const float* __restrict__ W,
               const float* __restrict__ bias, float* __restrict__ C,
               int N, int K) {
    extern __shared__ float sm[];

    const int tid  = threadIdx.x;
    const int wid  = tid / 32;
    const int lane = tid % 32;
    const int wm   = wid >> 1;       // 0..1
    const int wn   = wid & 1;        // 0..1
    const int g    = lane >> 2;      // 0..7
    const int t    = lane & 3;       // 0..3
    const int bx   = blockIdx.x;
    const int by   = blockIdx.y;

    const float* Ab = A + (size_t)(by * 128) * K;
    const float* Wb = W + (size_t)(bx * 128) * K;

    float acc[4][8][4];
    #pragma unroll
    for (int i = 0; i < 4; i++)
        #pragma unroll
        for (int j = 0; j < 8; j++)
            #pragma unroll
            for (int c = 0; c < 4; c++) acc[i][j][c] = 0.0f;

    const int crow = tid >> 3;           // 0..15
    const int ckc  = (tid & 7) * 4;      // 0..28

    const int ntiles = K / 32;

    auto load_tile = [&](int buf, int kt) {
        float* as = sm + buf * STAGE_F;
        float* bs = as + TILE_F;
        uint32_t as_u = smem_u32(as);
        uint32_t bs_u = smem_u32(bs);
        const float* Asrc = Ab + kt * 32;
        const float* Bsrc = Wb + kt * 32;
        #pragma unroll
        for (int i = 0; i < 8; i++) {
            int row = crow + i * 16;
            uint32_t doff = (uint32_t)(row * APAD + ckc) * 4u;
            cp16(as_u + doff, Asrc + (size_t)row * K + ckc);
            cp16(bs_u + doff, Bsrc + (size_t)row * K + ckc);
        }
        CP_COMMIT();
    };

    load_tile(0, 0);
    if (ntiles > 1) load_tile(1, 1);

    for (int kt = 0; kt < ntiles; kt++) {
        CP_WAIT(1);
        __syncthreads();                 // tile kt resident & visible

        const int buf = kt & 1;
        const float* as = sm + buf * STAGE_F + (wm * 64) * APAD;
        const float* bs = sm + buf * STAGE_F + TILE_F + (wn * 64) * APAD;

        #pragma unroll
        for (int ks = 0; ks < 4; ks++) {
            const int k0 = ks * 8 + 2 * t;   // interleaved: (t, t+4) contiguous
            uint32_t af[4][4], bf[8][2];
            #pragma unroll
            for (int mt = 0; mt < 4; mt++) {
                float2 lo = *(const float2*)(as + (mt * 16 + g) * APAD + k0);
                float2 hi = *(const float2*)(as + (mt * 16 + g + 8) * APAD + k0);
                af[mt][0] = __float_as_uint(lo.x);
                af[mt][1] = __float_as_uint(hi.x);
                af[mt][2] = __float_as_uint(lo.y);
                af[mt][3] = __float_as_uint(hi.y);
            }
            #pragma unroll
            for (int nt = 0; nt < 8; nt++) {
                float2 bb = *(const float2*)(bs + (nt * 8 + g) * APAD + k0);
                bf[nt][0] = __float_as_uint(bb.x);
                bf[nt][1] = __float_as_uint(bb.y);
            }
            #pragma unroll
            for (int mt = 0; mt < 4; mt++)
                #pragma unroll
                for (int nt = 0; nt < 8; nt++)
                    mma_tf32(acc[mt][nt], af[mt], bf[nt]);
        }

        __syncthreads();                 // all warps done reading buf
        if (kt + 2 < ntiles)
            load_tile(buf, kt + 2);      // reuse buf of tile kt
    }

    #pragma unroll
    for (int nt = 0; nt < 8; nt++) {
        const int col = bx * 128 + wn * 64 + nt * 8 + 2 * t;
        float2 bv = *(const float2*)(bias + col);
        #pragma unroll
        for (int mt = 0; mt < 4; mt++) {
            const int row = by * 128 + wm * 64 + mt * 16 + g;
            float2 r0, r1;
            r0.x = acc[mt][nt][0] + bv.x;
            r0.y = acc[mt][nt][1] + bv.y;
            r1.x = acc[mt][nt][2] + bv.x;
            r1.y = acc[mt][nt][3] + bv.y;
            *(float2*)(C + (size_t)row * N + col)       = r0;
            *(float2*)(C + (size_t)(row + 8) * N + col) = r1;
        }
    }
}

// ---------------------------------------------------------------------------
// Flash attention, element-wise repeated K/V. Writes att in the K-permuted
// layout consumed by tf32_gemm (GEMM2's A operand).
// ---------------------------------------------------------------------------
#define AT_BK 32

__global__ __launch_bounds__(256, 2)
void attn_kernel(const float* __restrict__ qkv, float* __restrict__ out) {
    __shared__ float Qs[32][32];
    __shared__ float Kt[32][33];
    __shared__ float Vs[AT_BK][32];

    const int qt   = blockIdx.x;
    const int h    = blockIdx.y;
    const int b    = blockIdx.z;
    const int tid  = threadIdx.x;
    const int wid  = tid / 32;
    const int lane = tid % 32;

    const float* base = qkv + (size_t)b * SEQT * QKVD;
    const float scale = 0.08838834764831845f;

    #pragma unroll
    for (int it = 0; it < 4; it++) {
        int r = it * 8 + wid;
        float4 q4 = *(const float4*)(base + (size_t)(qt * 32 + r) * QKVD + h * HD + lane * 4);
        Qs[r][lane] = (q4.x + q4.y + q4.z + q4.w) * scale;
    }

    float ov[4] = {0.f, 0.f, 0.f, 0.f};
    float m[4] = {-1e30f, -1e30f, -1e30f, -1e30f};
    float l[4] = {0.f, 0.f, 0.f, 0.f};
    const int qr0 = qt * 32 + wid * 4;

    const int ntiles = qt + 1;

    for (int tt = 0; tt < ntiles; tt++) {
        __syncthreads();
        {
            int r  = tid / 8;
            int d4 = (tid % 8) * 4;
            const float* rowp = base + (size_t)(tt * AT_BK + r) * QKVD + DIMX + h * 32 + d4;
            float4 kk = *(const float4*)(rowp);
            float4 vv = *(const float4*)(rowp + KVD);
            Kt[d4 + 0][r] = kk.x; Kt[d4 + 1][r] = kk.y;
            Kt[d4 + 2][r] = kk.z; Kt[d4 + 3][r] = kk.w;
            *(float4*)(&Vs[r][d4]) = vv;
        }
        __syncthreads();

        const int kg = tt * AT_BK + lane;

        #pragma unroll
        for (int i = 0; i < 4; i++) {
            const int q_row = qr0 + i;
            float s = 0.f;
            const float* qrow = Qs[wid * 4 + i];
            #pragma unroll
            for (int j = 0; j < 32; j++)
                s = fmaf(qrow[j], Kt[j][lane], s);
            if (kg > q_row) s = -1e30f;

            float mt = s;
            #pragma unroll
            for (int off = 16; off > 0; off >>= 1)
                mt = fmaxf(mt, __shfl_xor_sync(0xffffffffu, mt, off));
            float m_new = fmaxf(m[i], mt);
            float p = __expf(s - m_new);
            float alpha = __expf(m[i] - m_new);
            m[i] = m_new;

            float ps = p;
            #pragma unroll
            for (int off = 16; off > 0; off >>= 1)
                ps += __shfl_xor_sync(0xffffffffu, ps, off);
            l[i] = l[i] * alpha + ps;

            ov[i] *= alpha;
            #pragma unroll
            for (int k = 0; k < AT_BK; k++) {
                float pk = __shfl_sync(0xffffffffu, p, k);
                ov[i] = fmaf(pk, Vs[k][lane], ov[i]);
            }
        }
    }

    // permuted store: orig cols 4j..4j+3 (j=lane, all equal) map within their
    // k8 group to mem positions base8 + (j&1) + {0,2,4,6}
    #pragma unroll
    for (int i = 0; i < 4; i++) {
        float r = f2tf32f(ov[i] / l[i]);
        float* po = out + (size_t)(b * SEQT + qr0 + i) * DIMX
                    + h * HD + (lane >> 1) * 8 + (lane & 1);
        po[0] = r; po[2] = r; po[4] = r; po[6] = r;
    }
}

// ---------------------------------------------------------------------------
extern "C" void kernel_launch(void* const* d_in, const int* in_sizes, int n_in,
                              void* d_out, int out_size) {
    const float* x  = (const float*)d_in[0];
    const float* W1 = (const float*)d_in[1];
    const float* b1 = (const float*)d_in[2];
    const float* W2 = (const float*)d_in[3];
    const float* b2 = (const float*)d_in[4];
    float* out = (float*)d_out;

    float *qkv, *att, *xr, *w1r, *w2r;
    cudaGetSymbolAddress((void**)&qkv, g_qkv);
    cudaGetSymbolAddress((void**)&att, g_att);
    cudaGetSymbolAddress((void**)&xr,  g_xr);
    cudaGetSymbolAddress((void**)&w1r, g_w1r);
    cudaGetSymbolAddress((void**)&w2r, g_w2r);

    cudaFuncSetAttribute(tf32_gemm, cudaFuncAttributeMaxDynamicSharedMemorySize, GEMM_SMEM);

    const int M = NB * SEQT;

    {
        int n8 = (M * DIMX) / 8;
        round_perm<<<(n8 + 255) / 256, 256>>>(x, xr, n8);
        n8 = (QKVD * DIMX) / 8;
        round_perm<<<(n8 + 255) / 256, 256>>>(W1, w1r, n8);
        n8 = (DIMX * DIMX) / 8;
        round_perm<<<(n8 + 255) / 256, 256>>>(W2, w2r, n8);
    }

    dim3 g1(QKVD / 128, M / 128);
    tf32_gemm<<<g1, 128, GEMM_SMEM>>>(xr, w1r, b1, qkv, QKVD, DIMX);

    dim3 g2(SEQT / 32, NHEADS, NB);
    attn_kernel<<<g2, 256>>>(qkv, att);

    dim3 g3(DIMX / 128, M / 128);
    tf32_gemm<<<g3, 128, GEMM_SMEM>>>(att, w2r, b2, out, DIMX, DIMX);
}